// round 1
// baseline (speedup 1.0000x reference)
#include <cuda_runtime.h>
#include <cstdint>

#define NN 100000
#define NE 1600000

// ---------------- scratch (static __device__: no allocation allowed) ----------------
__device__ float g_h [NN * 128];   // current node features (max dim 128)
__device__ float g_hl[NN * 128];   // h @ Wl
__device__ float g_hr[NN * 128];   // h @ Wr
__device__ int   g_cnt[NN];
__device__ int   g_rowptr[NN + 1];
__device__ int   g_cursor[NN];
__device__ int   g_csrc[NE];
__device__ int   g_bsum[256];

// ---------------- CSR build ----------------
__global__ void k_count(const int* __restrict__ ei, int* __restrict__ cnt, int E) {
    int e = blockIdx.x * blockDim.x + threadIdx.x;
    if (e < E) atomicAdd(&cnt[ei[E + e]], 1);
}

__global__ void k_reduce(const int* __restrict__ cnt, int* __restrict__ bsum, int n) {
    __shared__ int ws[8];
    int base = blockIdx.x * 1024 + threadIdx.x * 4;
    int s = 0;
#pragma unroll
    for (int q = 0; q < 4; q++) { int idx = base + q; if (idx < n) s += cnt[idx]; }
#pragma unroll
    for (int d = 16; d; d >>= 1) s += __shfl_down_sync(0xffffffffu, s, d);
    if ((threadIdx.x & 31) == 0) ws[threadIdx.x >> 5] = s;
    __syncthreads();
    if (threadIdx.x == 0) {
        int t = 0;
#pragma unroll
        for (int i = 0; i < 8; i++) t += ws[i];
        bsum[blockIdx.x] = t;
    }
}

__global__ void k_spine(int* bsum, int nb) {
    if (blockIdx.x == 0 && threadIdx.x == 0) {
        int run = 0;
        for (int i = 0; i < nb; i++) { int t = bsum[i]; bsum[i] = run; run += t; }
    }
}

__global__ void k_scan(const int* __restrict__ cnt, const int* __restrict__ bofs,
                       int* __restrict__ rowptr, int n) {
    __shared__ int ws[8];
    int base = blockIdx.x * 1024 + threadIdx.x * 4;
    int c[4];
#pragma unroll
    for (int q = 0; q < 4; q++) { int idx = base + q; c[q] = (idx < n) ? cnt[idx] : 0; }
    int s1 = c[0], s2 = s1 + c[1], s3 = s2 + c[2], s4 = s3 + c[3];
    int lane = threadIdx.x & 31, w = threadIdx.x >> 5;
    int v = s4;
#pragma unroll
    for (int d = 1; d < 32; d <<= 1) {
        int u = __shfl_up_sync(0xffffffffu, v, d);
        if (lane >= d) v += u;
    }
    int texcl = v - s4;
    if (lane == 31) ws[w] = v;
    __syncthreads();
    if (threadIdx.x == 0) {
        int run = 0;
        for (int i = 0; i < 8; i++) { int t = ws[i]; ws[i] = run; run += t; }
    }
    __syncthreads();
    int ofs = bofs[blockIdx.x] + ws[w] + texcl;
    int sv[4] = {s1, s2, s3, s4};
#pragma unroll
    for (int q = 0; q < 4; q++) { int idx = base + q; if (idx < n) rowptr[idx + 1] = ofs + sv[q]; }
    if (blockIdx.x == 0 && threadIdx.x == 0) rowptr[0] = 0;
}

__global__ void k_fill(const int* __restrict__ ei, int* __restrict__ cursor,
                       int* __restrict__ csrc, int E) {
    int e = blockIdx.x * blockDim.x + threadIdx.x;
    if (e < E) {
        int s = ei[e], d = ei[E + e];
        int p = atomicAdd(&cursor[d], 1);
        csrc[p] = s;
    }
}

// ---------------- layer 1: mean-agg in dim 2, then tiny GEMM (2->128) fused ----------------
__global__ void k_layer1(const float* __restrict__ x, const int* __restrict__ rowptr,
                         const int* __restrict__ csrc,
                         const float* __restrict__ Wl, const float* __restrict__ bl,
                         const float* __restrict__ Wr,
                         float* __restrict__ hout, int n) {
    __shared__ float sWl[256], sWr[256], sbl[128];
    for (int i = threadIdx.x; i < 256; i += blockDim.x) { sWl[i] = Wl[i]; sWr[i] = Wr[i]; }
    for (int i = threadIdx.x; i < 128; i += blockDim.x) sbl[i] = bl[i];
    __syncthreads();
    int gw = (blockIdx.x * blockDim.x + threadIdx.x) >> 5;
    int lane = threadIdx.x & 31;
    if (gw >= n) return;
    int rs = rowptr[gw], re = rowptr[gw + 1];
    float ax = 0.f, ay = 0.f;
    for (int t = rs + lane; t < re; t += 32) {
        int s = csrc[t];
        float2 v = *(const float2*)&x[2 * s];
        ax += v.x; ay += v.y;
    }
#pragma unroll
    for (int d = 16; d; d >>= 1) {
        ax += __shfl_xor_sync(0xffffffffu, ax, d);
        ay += __shfl_xor_sync(0xffffffffu, ay, d);
    }
    float dv = (float)(re - rs);
    float inv = 1.0f / fmaxf(dv, 1.0f);
    ax *= inv; ay *= inv;
    float2 xv = *(const float2*)&x[2 * gw];
    int j = lane * 4;
    float4 o;
    o.x = fmaxf(ax * sWl[j + 0] + ay * sWl[128 + j + 0] + sbl[j + 0] + xv.x * sWr[j + 0] + xv.y * sWr[128 + j + 0], 0.f);
    o.y = fmaxf(ax * sWl[j + 1] + ay * sWl[128 + j + 1] + sbl[j + 1] + xv.x * sWr[j + 1] + xv.y * sWr[128 + j + 1], 0.f);
    o.z = fmaxf(ax * sWl[j + 2] + ay * sWl[128 + j + 2] + sbl[j + 2] + xv.x * sWr[j + 2] + xv.y * sWr[128 + j + 2], 0.f);
    o.w = fmaxf(ax * sWl[j + 3] + ay * sWl[128 + j + 3] + sbl[j + 3] + xv.x * sWr[j + 3] + xv.y * sWr[128 + j + 3], 0.f);
    *(float4*)&hout[gw * 128 + j] = o;
}

// ---------------- fused GEMM: C = A[n,K] @ [Wl | Wr]  (f32x2 packed FMA) ----------------
template <int K, int NT>
__launch_bounds__(256, 1)
__global__ void k_gemm(const float* __restrict__ A, const float* __restrict__ W0,
                       const float* __restrict__ W1,
                       float* __restrict__ Cl, float* __restrict__ Cr, int n) {
    constexpr int BM = 128;
    constexpr int TN = NT / 16;
    constexpr int COUT = NT / 2;
    extern __shared__ float smem[];
    float* As = smem;            // [BM][K]
    float* Bs = smem + BM * K;   // [K][NT]
    int tid = threadIdx.x;
    int row0 = blockIdx.x * BM;

    for (int i = tid; i < K * NT / 4; i += 256) {
        int f = i * 4;
        int k = f / NT;
        int j = f - k * NT;
        float4 v;
        if (j < COUT) v = *(const float4*)&W0[k * COUT + j];
        else          v = *(const float4*)&W1[k * COUT + j - COUT];
        *(float4*)&Bs[f] = v;
    }
    for (int i = tid; i < BM * K / 4; i += 256) {
        int f = i * 4;
        int m = f / K;
        int k = f - m * K;
        int row = row0 + m;
        float4 v = make_float4(0.f, 0.f, 0.f, 0.f);
        if (row < n) v = *(const float4*)&A[row * K + k];
        *(float4*)&As[f] = v;
    }
    __syncthreads();

    int ty = tid >> 4, tx = tid & 15;
    int m0 = ty * 8, n0 = tx * TN;

    unsigned long long acc[8][TN / 2];
#pragma unroll
    for (int i = 0; i < 8; i++)
#pragma unroll
        for (int j = 0; j < TN / 2; j++) acc[i][j] = 0ull;

#pragma unroll 2
    for (int kk = 0; kk < K; kk += 4) {
        float a[8][4];
#pragma unroll
        for (int i = 0; i < 8; i++) {
            float4 v = *(const float4*)&As[(m0 + i) * K + kk];
            a[i][0] = v.x; a[i][1] = v.y; a[i][2] = v.z; a[i][3] = v.w;
        }
#pragma unroll
        for (int dk = 0; dk < 4; dk++) {
            unsigned long long bq[TN / 2];
#pragma unroll
            for (int j = 0; j < TN / 2; j++)
                bq[j] = *(const unsigned long long*)&Bs[(kk + dk) * NT + n0 + 2 * j];
#pragma unroll
            for (int i = 0; i < 8; i++) {
                unsigned long long a2;
                asm("mov.b64 %0, {%1, %2};" : "=l"(a2) : "f"(a[i][dk]), "f"(a[i][dk]));
#pragma unroll
                for (int j = 0; j < TN / 2; j++)
                    asm("fma.rn.f32x2 %0, %1, %2, %0;" : "+l"(acc[i][j]) : "l"(a2), "l"(bq[j]));
            }
        }
    }

    float* Cbase = (n0 < COUT) ? (Cl + n0) : (Cr + (n0 - COUT));
#pragma unroll
    for (int i = 0; i < 8; i++) {
        int row = row0 + m0 + i;
        if (row < n) {
#pragma unroll
            for (int j4 = 0; j4 < TN / 4; j4++) {
                float lo0, hi0, lo1, hi1;
                asm("mov.b64 {%0, %1}, %2;" : "=f"(lo0), "=f"(hi0) : "l"(acc[i][2 * j4 + 0]));
                asm("mov.b64 {%0, %1}, %2;" : "=f"(lo1), "=f"(hi1) : "l"(acc[i][2 * j4 + 1]));
                float4 v = make_float4(lo0, hi0, lo1, hi1);
                *(float4*)&Cbase[row * COUT + j4 * 4] = v;
            }
        }
    }
}

// ---------------- post: h = relu(mean_agg(hl) + bl + hr), CSR gather, D cols ----------------
template <int D>
__global__ void k_post(const int* __restrict__ rowptr, const int* __restrict__ csrc,
                       const float* __restrict__ hl, const float* __restrict__ hr,
                       const float* __restrict__ bl, float* __restrict__ hout, int n) {
    constexpr int LPN = D / 4;
    int tid = blockIdx.x * blockDim.x + threadIdx.x;
    int node = tid / LPN;
    int sub = tid % LPN;
    if (node >= n) return;
    int rs = rowptr[node], re = rowptr[node + 1];
    float4 acc = make_float4(0.f, 0.f, 0.f, 0.f);
    int t = rs;
    for (; t + 1 < re; t += 2) {
        int s0 = csrc[t], s1 = csrc[t + 1];
        float4 v0 = *(const float4*)&hl[s0 * D + sub * 4];
        float4 v1 = *(const float4*)&hl[s1 * D + sub * 4];
        acc.x += v0.x + v1.x; acc.y += v0.y + v1.y;
        acc.z += v0.z + v1.z; acc.w += v0.w + v1.w;
    }
    if (t < re) {
        int s0 = csrc[t];
        float4 v0 = *(const float4*)&hl[s0 * D + sub * 4];
        acc.x += v0.x; acc.y += v0.y; acc.z += v0.z; acc.w += v0.w;
    }
    float dv = (float)(re - rs);
    float inv = 1.0f / fmaxf(dv, 1.0f);
    float4 r = *(const float4*)&hr[node * D + sub * 4];
    float4 b = *(const float4*)&bl[sub * 4];
    float4 o;
    o.x = fmaxf(acc.x * inv + b.x + r.x, 0.f);
    o.y = fmaxf(acc.y * inv + b.y + r.y, 0.f);
    o.z = fmaxf(acc.z * inv + b.z + r.z, 0.f);
    o.w = fmaxf(acc.w * inv + b.w + r.w, 0.f);
    *(float4*)&hout[node * D + sub * 4] = o;
}

// ---------------- output head: out[i] = h5[i,:] . W_out + b_out ----------------
__global__ void k_out(const float* __restrict__ h, const float* __restrict__ W,
                      const float* __restrict__ b, float* __restrict__ out, int n) {
    int tid = blockIdx.x * blockDim.x + threadIdx.x;
    int node = tid >> 3;
    int sub = tid & 7;
    if (node >= n) return;
    float4 hv = *(const float4*)&h[node * 32 + sub * 4];
    float4 wv = *(const float4*)&W[sub * 4];
    float s = hv.x * wv.x + hv.y * wv.y + hv.z * wv.z + hv.w * wv.w;
    s += __shfl_down_sync(0xffffffffu, s, 4);
    s += __shfl_down_sync(0xffffffffu, s, 2);
    s += __shfl_down_sync(0xffffffffu, s, 1);
    if (sub == 0) out[node] = s + b[0];
}

// ---------------- launch ----------------
extern "C" void kernel_launch(void* const* d_in, const int* in_sizes, int n_in,
                              void* d_out, int out_size) {
    const float* x   = (const float*)d_in[0];
    const int*   ei  = (const int*)d_in[1];
    const float* Wl1 = (const float*)d_in[3];
    const float* bl1 = (const float*)d_in[4];
    const float* Wr1 = (const float*)d_in[5];
    const float* Wl2 = (const float*)d_in[6];
    const float* bl2 = (const float*)d_in[7];
    const float* Wr2 = (const float*)d_in[8];
    const float* Wl3 = (const float*)d_in[9];
    const float* bl3 = (const float*)d_in[10];
    const float* Wr3 = (const float*)d_in[11];
    const float* Wl4 = (const float*)d_in[12];
    const float* bl4 = (const float*)d_in[13];
    const float* Wr4 = (const float*)d_in[14];
    const float* Wl5 = (const float*)d_in[15];
    const float* bl5 = (const float*)d_in[16];
    const float* Wr5 = (const float*)d_in[17];
    const float* Wo  = (const float*)d_in[18];
    const float* bo  = (const float*)d_in[19];
    float* out = (float*)d_out;

    int n = in_sizes[0] / 2;
    int E = in_sizes[1] / 2;

    float *p_h, *p_hl, *p_hr;
    int *p_cnt, *p_rowptr, *p_cursor, *p_csrc, *p_bsum;
    cudaGetSymbolAddress((void**)&p_h, g_h);
    cudaGetSymbolAddress((void**)&p_hl, g_hl);
    cudaGetSymbolAddress((void**)&p_hr, g_hr);
    cudaGetSymbolAddress((void**)&p_cnt, g_cnt);
    cudaGetSymbolAddress((void**)&p_rowptr, g_rowptr);
    cudaGetSymbolAddress((void**)&p_cursor, g_cursor);
    cudaGetSymbolAddress((void**)&p_csrc, g_csrc);
    cudaGetSymbolAddress((void**)&p_bsum, g_bsum);

    cudaFuncSetAttribute(k_gemm<128, 256>, cudaFuncAttributeMaxDynamicSharedMemorySize, 196608);
    cudaFuncSetAttribute(k_gemm<128, 64>,  cudaFuncAttributeMaxDynamicSharedMemorySize, 98304);
    cudaFuncSetAttribute(k_gemm<32, 64>,   cudaFuncAttributeMaxDynamicSharedMemorySize, 24576);

    int NB = (n + 1023) / 1024;
    int eg = (E + 255) / 256;
    int gb = (n + 127) / 128;
    int g_warp = (n * 32 + 255) / 256;   // one warp per node
    int g_oct  = (n * 8 + 255) / 256;    // 8 lanes per node

    // CSR build (also yields degrees via rowptr diffs)
    cudaMemsetAsync(p_cnt, 0, n * sizeof(int));
    k_count<<<eg, 256>>>(ei, p_cnt, E);
    k_reduce<<<NB, 256>>>(p_cnt, p_bsum, n);
    k_spine<<<1, 1>>>(p_bsum, NB);
    k_scan<<<NB, 256>>>(p_cnt, p_bsum, p_rowptr, n);
    cudaMemcpyAsync(p_cursor, p_rowptr, n * sizeof(int), cudaMemcpyDeviceToDevice);
    k_fill<<<eg, 256>>>(ei, p_cursor, p_csrc, E);

    // layer 1 (2 -> 128): aggregate in dim 2, fused GEMM
    k_layer1<<<g_warp, 256>>>(x, p_rowptr, p_csrc, Wl1, bl1, Wr1, p_h, n);

    // layer 2 (128 -> 128)
    k_gemm<128, 256><<<gb, 256, 196608>>>(p_h, Wl2, Wr2, p_hl, p_hr, n);
    k_post<128><<<g_warp, 256>>>(p_rowptr, p_csrc, p_hl, p_hr, bl2, p_h, n);

    // layer 3 (128 -> 32)
    k_gemm<128, 64><<<gb, 256, 98304>>>(p_h, Wl3, Wr3, p_hl, p_hr, n);
    k_post<32><<<g_oct, 256>>>(p_rowptr, p_csrc, p_hl, p_hr, bl3, p_h, n);

    // layer 4 (32 -> 32)
    k_gemm<32, 64><<<gb, 256, 24576>>>(p_h, Wl4, Wr4, p_hl, p_hr, n);
    k_post<32><<<g_oct, 256>>>(p_rowptr, p_csrc, p_hl, p_hr, bl4, p_h, n);

    // layer 5 (32 -> 32)
    k_gemm<32, 64><<<gb, 256, 24576>>>(p_h, Wl5, Wr5, p_hl, p_hr, n);
    k_post<32><<<g_oct, 256>>>(p_rowptr, p_csrc, p_hl, p_hr, bl5, p_h, n);

    // output head
    k_out<<<g_oct, 256>>>(p_h, Wo, bo, out, n);
}

// round 2
// speedup vs baseline: 1.0898x; 1.0898x over previous
#include <cuda_runtime.h>
#include <cuda_fp16.h>
#include <cstdint>

#define NN 100000
#define NE 1600000

// ---------------- scratch (static __device__: no allocation allowed) ----------------
__device__ float  g_h [NN * 128];   // current node features (fp32, GEMM input)
__device__ __half g_hl[NN * 128];   // h @ Wl (fp16: gathered operand)
__device__ float  g_hr[NN * 128];   // h @ Wr (fp32: read once, coalesced)
__device__ int    g_cnt[NN];
__device__ int    g_rowptr[NN + 1];
__device__ int    g_cursor[NN];
__device__ int    g_csrc[NE];
__device__ int    g_bsum[256];

// ---------------- CSR build ----------------
__global__ void k_count(const int* __restrict__ ei, int* __restrict__ cnt, int E) {
    int e = blockIdx.x * blockDim.x + threadIdx.x;
    if (e < E) atomicAdd(&cnt[ei[E + e]], 1);
}

__global__ void k_reduce(const int* __restrict__ cnt, int* __restrict__ bsum, int n) {
    __shared__ int ws[8];
    int base = blockIdx.x * 1024 + threadIdx.x * 4;
    int s = 0;
#pragma unroll
    for (int q = 0; q < 4; q++) { int idx = base + q; if (idx < n) s += cnt[idx]; }
#pragma unroll
    for (int d = 16; d; d >>= 1) s += __shfl_down_sync(0xffffffffu, s, d);
    if ((threadIdx.x & 31) == 0) ws[threadIdx.x >> 5] = s;
    __syncthreads();
    if (threadIdx.x == 0) {
        int t = 0;
#pragma unroll
        for (int i = 0; i < 8; i++) t += ws[i];
        bsum[blockIdx.x] = t;
    }
}

__global__ void k_spine(int* bsum, int nb) {
    if (blockIdx.x == 0 && threadIdx.x == 0) {
        int run = 0;
        for (int i = 0; i < nb; i++) { int t = bsum[i]; bsum[i] = run; run += t; }
    }
}

__global__ void k_scan(const int* __restrict__ cnt, const int* __restrict__ bofs,
                       int* __restrict__ rowptr, int n) {
    __shared__ int ws[8];
    int base = blockIdx.x * 1024 + threadIdx.x * 4;
    int c[4];
#pragma unroll
    for (int q = 0; q < 4; q++) { int idx = base + q; c[q] = (idx < n) ? cnt[idx] : 0; }
    int s1 = c[0], s2 = s1 + c[1], s3 = s2 + c[2], s4 = s3 + c[3];
    int lane = threadIdx.x & 31, w = threadIdx.x >> 5;
    int v = s4;
#pragma unroll
    for (int d = 1; d < 32; d <<= 1) {
        int u = __shfl_up_sync(0xffffffffu, v, d);
        if (lane >= d) v += u;
    }
    int texcl = v - s4;
    if (lane == 31) ws[w] = v;
    __syncthreads();
    if (threadIdx.x == 0) {
        int run = 0;
        for (int i = 0; i < 8; i++) { int t = ws[i]; ws[i] = run; run += t; }
    }
    __syncthreads();
    int ofs = bofs[blockIdx.x] + ws[w] + texcl;
    int sv[4] = {s1, s2, s3, s4};
#pragma unroll
    for (int q = 0; q < 4; q++) { int idx = base + q; if (idx < n) rowptr[idx + 1] = ofs + sv[q]; }
    if (blockIdx.x == 0 && threadIdx.x == 0) rowptr[0] = 0;
}

__global__ void k_fill(const int* __restrict__ ei, int* __restrict__ cursor,
                       int* __restrict__ csrc, int E) {
    int e = blockIdx.x * blockDim.x + threadIdx.x;
    if (e < E) {
        int s = ei[e], d = ei[E + e];
        int p = atomicAdd(&cursor[d], 1);
        csrc[p] = s;
    }
}

// ---------------- layer 1: mean-agg in dim 2, then tiny GEMM (2->128) fused ----------------
__global__ void k_layer1(const float* __restrict__ x, const int* __restrict__ rowptr,
                         const int* __restrict__ csrc,
                         const float* __restrict__ Wl, const float* __restrict__ bl,
                         const float* __restrict__ Wr,
                         float* __restrict__ hout, int n) {
    __shared__ float sWl[256], sWr[256], sbl[128];
    for (int i = threadIdx.x; i < 256; i += blockDim.x) { sWl[i] = Wl[i]; sWr[i] = Wr[i]; }
    for (int i = threadIdx.x; i < 128; i += blockDim.x) sbl[i] = bl[i];
    __syncthreads();
    int gw = (blockIdx.x * blockDim.x + threadIdx.x) >> 5;
    int lane = threadIdx.x & 31;
    if (gw >= n) return;
    int rs = rowptr[gw], re = rowptr[gw + 1];
    float ax = 0.f, ay = 0.f;
    for (int t = rs + lane; t < re; t += 32) {
        int s = csrc[t];
        float2 v = *(const float2*)&x[2 * s];
        ax += v.x; ay += v.y;
    }
#pragma unroll
    for (int d = 16; d; d >>= 1) {
        ax += __shfl_xor_sync(0xffffffffu, ax, d);
        ay += __shfl_xor_sync(0xffffffffu, ay, d);
    }
    float dv = (float)(re - rs);
    float inv = 1.0f / fmaxf(dv, 1.0f);
    ax *= inv; ay *= inv;
    float2 xv = *(const float2*)&x[2 * gw];
    int j = lane * 4;
    float4 o;
    o.x = fmaxf(ax * sWl[j + 0] + ay * sWl[128 + j + 0] + sbl[j + 0] + xv.x * sWr[j + 0] + xv.y * sWr[128 + j + 0], 0.f);
    o.y = fmaxf(ax * sWl[j + 1] + ay * sWl[128 + j + 1] + sbl[j + 1] + xv.x * sWr[j + 1] + xv.y * sWr[128 + j + 1], 0.f);
    o.z = fmaxf(ax * sWl[j + 2] + ay * sWl[128 + j + 2] + sbl[j + 2] + xv.x * sWr[j + 2] + xv.y * sWr[128 + j + 2], 0.f);
    o.w = fmaxf(ax * sWl[j + 3] + ay * sWl[128 + j + 3] + sbl[j + 3] + xv.x * sWr[j + 3] + xv.y * sWr[128 + j + 3], 0.f);
    *(float4*)&hout[gw * 128 + j] = o;
}

// ---------------- fused GEMM: [Cl(fp16) | Cr(fp32)] = A[n,K] @ [Wl | Wr] ----------------
template <int K, int NT>
__launch_bounds__(256, 1)
__global__ void k_gemm(const float* __restrict__ A, const float* __restrict__ W0,
                       const float* __restrict__ W1,
                       __half* __restrict__ Cl, float* __restrict__ Cr, int n) {
    constexpr int BM = 128;
    constexpr int TN = NT / 16;
    constexpr int COUT = NT / 2;
    extern __shared__ float smem[];
    float* As = smem;            // [BM][K]
    float* Bs = smem + BM * K;   // [K][NT]
    int tid = threadIdx.x;
    int row0 = blockIdx.x * BM;

    for (int i = tid; i < K * NT / 4; i += 256) {
        int f = i * 4;
        int k = f / NT;
        int j = f - k * NT;
        float4 v;
        if (j < COUT) v = *(const float4*)&W0[k * COUT + j];
        else          v = *(const float4*)&W1[k * COUT + j - COUT];
        *(float4*)&Bs[f] = v;
    }
    for (int i = tid; i < BM * K / 4; i += 256) {
        int f = i * 4;
        int m = f / K;
        int k = f - m * K;
        int row = row0 + m;
        float4 v = make_float4(0.f, 0.f, 0.f, 0.f);
        if (row < n) v = *(const float4*)&A[row * K + k];
        *(float4*)&As[f] = v;
    }
    __syncthreads();

    int ty = tid >> 4, tx = tid & 15;
    int m0 = ty * 8, n0 = tx * TN;

    unsigned long long acc[8][TN / 2];
#pragma unroll
    for (int i = 0; i < 8; i++)
#pragma unroll
        for (int j = 0; j < TN / 2; j++) acc[i][j] = 0ull;

#pragma unroll 2
    for (int kk = 0; kk < K; kk += 4) {
        float a[8][4];
#pragma unroll
        for (int i = 0; i < 8; i++) {
            float4 v = *(const float4*)&As[(m0 + i) * K + kk];
            a[i][0] = v.x; a[i][1] = v.y; a[i][2] = v.z; a[i][3] = v.w;
        }
#pragma unroll
        for (int dk = 0; dk < 4; dk++) {
            unsigned long long bq[TN / 2];
#pragma unroll
            for (int j = 0; j < TN / 2; j++)
                bq[j] = *(const unsigned long long*)&Bs[(kk + dk) * NT + n0 + 2 * j];
#pragma unroll
            for (int i = 0; i < 8; i++) {
                unsigned long long a2;
                asm("mov.b64 %0, {%1, %2};" : "=l"(a2) : "f"(a[i][dk]), "f"(a[i][dk]));
#pragma unroll
                for (int j = 0; j < TN / 2; j++)
                    asm("fma.rn.f32x2 %0, %1, %2, %0;" : "+l"(acc[i][j]) : "l"(a2), "l"(bq[j]));
            }
        }
    }

    if (n0 < COUT) {
        // fp16 output path (Cl)
        __half* C = Cl + n0;
#pragma unroll
        for (int i = 0; i < 8; i++) {
            int row = row0 + m0 + i;
            if (row < n) {
#pragma unroll
                for (int j4 = 0; j4 < TN / 4; j4++) {
                    float lo0, hi0, lo1, hi1;
                    asm("mov.b64 {%0, %1}, %2;" : "=f"(lo0), "=f"(hi0) : "l"(acc[i][2 * j4 + 0]));
                    asm("mov.b64 {%0, %1}, %2;" : "=f"(lo1), "=f"(hi1) : "l"(acc[i][2 * j4 + 1]));
                    __half2 h0 = __floats2half2_rn(lo0, hi0);
                    __half2 h1 = __floats2half2_rn(lo1, hi1);
                    uint2 v;
                    v.x = *(unsigned*)&h0;
                    v.y = *(unsigned*)&h1;
                    *(uint2*)&C[row * COUT + j4 * 4] = v;
                }
            }
        }
    } else {
        float* C = Cr + (n0 - COUT);
#pragma unroll
        for (int i = 0; i < 8; i++) {
            int row = row0 + m0 + i;
            if (row < n) {
#pragma unroll
                for (int j4 = 0; j4 < TN / 4; j4++) {
                    float lo0, hi0, lo1, hi1;
                    asm("mov.b64 {%0, %1}, %2;" : "=f"(lo0), "=f"(hi0) : "l"(acc[i][2 * j4 + 0]));
                    asm("mov.b64 {%0, %1}, %2;" : "=f"(lo1), "=f"(hi1) : "l"(acc[i][2 * j4 + 1]));
                    float4 v = make_float4(lo0, hi0, lo1, hi1);
                    *(float4*)&C[row * COUT + j4 * 4] = v;
                }
            }
        }
    }
}

// ---------------- post: h = relu(mean_agg(hl fp16) + bl + hr), CSR gather ----------------
// LPN = D/8 lanes per node, 8 halves (16B) per lane per edge.
template <int D>
__global__ void k_post(const int* __restrict__ rowptr, const int* __restrict__ csrc,
                       const __half* __restrict__ hl, const float* __restrict__ hr,
                       const float* __restrict__ bl, float* __restrict__ hout, int n) {
    constexpr int LPN = D / 8;
    int tid = blockIdx.x * blockDim.x + threadIdx.x;
    int node = tid / LPN;
    int sub = tid % LPN;
    if (node >= n) return;
    int rs = rowptr[node], re = rowptr[node + 1];
    float a0 = 0.f, a1 = 0.f, a2 = 0.f, a3 = 0.f, a4 = 0.f, a5 = 0.f, a6 = 0.f, a7 = 0.f;
    int t = rs;
    for (; t + 1 < re; t += 2) {
        int s0 = csrc[t], s1 = csrc[t + 1];
        uint4 v0 = *(const uint4*)&hl[s0 * D + sub * 8];
        uint4 v1 = *(const uint4*)&hl[s1 * D + sub * 8];
        float2 f;
        f = __half22float2(*(__half2*)&v0.x); a0 += f.x; a1 += f.y;
        f = __half22float2(*(__half2*)&v0.y); a2 += f.x; a3 += f.y;
        f = __half22float2(*(__half2*)&v0.z); a4 += f.x; a5 += f.y;
        f = __half22float2(*(__half2*)&v0.w); a6 += f.x; a7 += f.y;
        f = __half22float2(*(__half2*)&v1.x); a0 += f.x; a1 += f.y;
        f = __half22float2(*(__half2*)&v1.y); a2 += f.x; a3 += f.y;
        f = __half22float2(*(__half2*)&v1.z); a4 += f.x; a5 += f.y;
        f = __half22float2(*(__half2*)&v1.w); a6 += f.x; a7 += f.y;
    }
    if (t < re) {
        int s0 = csrc[t];
        uint4 v0 = *(const uint4*)&hl[s0 * D + sub * 8];
        float2 f;
        f = __half22float2(*(__half2*)&v0.x); a0 += f.x; a1 += f.y;
        f = __half22float2(*(__half2*)&v0.y); a2 += f.x; a3 += f.y;
        f = __half22float2(*(__half2*)&v0.z); a4 += f.x; a5 += f.y;
        f = __half22float2(*(__half2*)&v0.w); a6 += f.x; a7 += f.y;
    }
    float dv = (float)(re - rs);
    float inv = 1.0f / fmaxf(dv, 1.0f);
    float4 r0 = *(const float4*)&hr[node * D + sub * 8];
    float4 r1 = *(const float4*)&hr[node * D + sub * 8 + 4];
    float4 b0 = *(const float4*)&bl[sub * 8];
    float4 b1 = *(const float4*)&bl[sub * 8 + 4];
    float4 o0, o1;
    o0.x = fmaxf(a0 * inv + b0.x + r0.x, 0.f);
    o0.y = fmaxf(a1 * inv + b0.y + r0.y, 0.f);
    o0.z = fmaxf(a2 * inv + b0.z + r0.z, 0.f);
    o0.w = fmaxf(a3 * inv + b0.w + r0.w, 0.f);
    o1.x = fmaxf(a4 * inv + b1.x + r1.x, 0.f);
    o1.y = fmaxf(a5 * inv + b1.y + r1.y, 0.f);
    o1.z = fmaxf(a6 * inv + b1.z + r1.z, 0.f);
    o1.w = fmaxf(a7 * inv + b1.w + r1.w, 0.f);
    *(float4*)&hout[node * D + sub * 8] = o0;
    *(float4*)&hout[node * D + sub * 8 + 4] = o1;
}

// ---------------- layer 5 post fused with output head: out[node] = h5 . W_out + b_out ----
__global__ void k_post_out(const int* __restrict__ rowptr, const int* __restrict__ csrc,
                           const __half* __restrict__ hl, const float* __restrict__ hr,
                           const float* __restrict__ bl,
                           const float* __restrict__ Wo, const float* __restrict__ bo,
                           float* __restrict__ out, int n) {
    constexpr int D = 32;
    constexpr int LPN = 4;
    int tid = blockIdx.x * blockDim.x + threadIdx.x;
    int node = tid / LPN;
    int sub = tid % LPN;
    if (node >= n) return;
    int rs = rowptr[node], re = rowptr[node + 1];
    float a0 = 0.f, a1 = 0.f, a2 = 0.f, a3 = 0.f, a4 = 0.f, a5 = 0.f, a6 = 0.f, a7 = 0.f;
    int t = rs;
    for (; t + 1 < re; t += 2) {
        int s0 = csrc[t], s1 = csrc[t + 1];
        uint4 v0 = *(const uint4*)&hl[s0 * D + sub * 8];
        uint4 v1 = *(const uint4*)&hl[s1 * D + sub * 8];
        float2 f;
        f = __half22float2(*(__half2*)&v0.x); a0 += f.x; a1 += f.y;
        f = __half22float2(*(__half2*)&v0.y); a2 += f.x; a3 += f.y;
        f = __half22float2(*(__half2*)&v0.z); a4 += f.x; a5 += f.y;
        f = __half22float2(*(__half2*)&v0.w); a6 += f.x; a7 += f.y;
        f = __half22float2(*(__half2*)&v1.x); a0 += f.x; a1 += f.y;
        f = __half22float2(*(__half2*)&v1.y); a2 += f.x; a3 += f.y;
        f = __half22float2(*(__half2*)&v1.z); a4 += f.x; a5 += f.y;
        f = __half22float2(*(__half2*)&v1.w); a6 += f.x; a7 += f.y;
    }
    if (t < re) {
        int s0 = csrc[t];
        uint4 v0 = *(const uint4*)&hl[s0 * D + sub * 8];
        float2 f;
        f = __half22float2(*(__half2*)&v0.x); a0 += f.x; a1 += f.y;
        f = __half22float2(*(__half2*)&v0.y); a2 += f.x; a3 += f.y;
        f = __half22float2(*(__half2*)&v0.z); a4 += f.x; a5 += f.y;
        f = __half22float2(*(__half2*)&v0.w); a6 += f.x; a7 += f.y;
    }
    float dv = (float)(re - rs);
    float inv = 1.0f / fmaxf(dv, 1.0f);
    float4 r0 = *(const float4*)&hr[node * D + sub * 8];
    float4 r1 = *(const float4*)&hr[node * D + sub * 8 + 4];
    float4 b0 = *(const float4*)&bl[sub * 8];
    float4 b1 = *(const float4*)&bl[sub * 8 + 4];
    float4 w0 = *(const float4*)&Wo[sub * 8];
    float4 w1 = *(const float4*)&Wo[sub * 8 + 4];
    float s = 0.f;
    s += fmaxf(a0 * inv + b0.x + r0.x, 0.f) * w0.x;
    s += fmaxf(a1 * inv + b0.y + r0.y, 0.f) * w0.y;
    s += fmaxf(a2 * inv + b0.z + r0.z, 0.f) * w0.z;
    s += fmaxf(a3 * inv + b0.w + r0.w, 0.f) * w0.w;
    s += fmaxf(a4 * inv + b1.x + r1.x, 0.f) * w1.x;
    s += fmaxf(a5 * inv + b1.y + r1.y, 0.f) * w1.y;
    s += fmaxf(a6 * inv + b1.z + r1.z, 0.f) * w1.z;
    s += fmaxf(a7 * inv + b1.w + r1.w, 0.f) * w1.w;
    s += __shfl_xor_sync(0xffffffffu, s, 1);
    s += __shfl_xor_sync(0xffffffffu, s, 2);
    if (sub == 0) out[node] = s + bo[0];
}

// ---------------- launch ----------------
extern "C" void kernel_launch(void* const* d_in, const int* in_sizes, int n_in,
                              void* d_out, int out_size) {
    const float* x   = (const float*)d_in[0];
    const int*   ei  = (const int*)d_in[1];
    const float* Wl1 = (const float*)d_in[3];
    const float* bl1 = (const float*)d_in[4];
    const float* Wr1 = (const float*)d_in[5];
    const float* Wl2 = (const float*)d_in[6];
    const float* bl2 = (const float*)d_in[7];
    const float* Wr2 = (const float*)d_in[8];
    const float* Wl3 = (const float*)d_in[9];
    const float* bl3 = (const float*)d_in[10];
    const float* Wr3 = (const float*)d_in[11];
    const float* Wl4 = (const float*)d_in[12];
    const float* bl4 = (const float*)d_in[13];
    const float* Wr4 = (const float*)d_in[14];
    const float* Wl5 = (const float*)d_in[15];
    const float* bl5 = (const float*)d_in[16];
    const float* Wr5 = (const float*)d_in[17];
    const float* Wo  = (const float*)d_in[18];
    const float* bo  = (const float*)d_in[19];
    float* out = (float*)d_out;

    int n = in_sizes[0] / 2;
    int E = in_sizes[1] / 2;

    float *p_h, *p_hr;
    __half* p_hl;
    int *p_cnt, *p_rowptr, *p_cursor, *p_csrc, *p_bsum;
    cudaGetSymbolAddress((void**)&p_h, g_h);
    cudaGetSymbolAddress((void**)&p_hl, g_hl);
    cudaGetSymbolAddress((void**)&p_hr, g_hr);
    cudaGetSymbolAddress((void**)&p_cnt, g_cnt);
    cudaGetSymbolAddress((void**)&p_rowptr, g_rowptr);
    cudaGetSymbolAddress((void**)&p_cursor, g_cursor);
    cudaGetSymbolAddress((void**)&p_csrc, g_csrc);
    cudaGetSymbolAddress((void**)&p_bsum, g_bsum);

    cudaFuncSetAttribute(k_gemm<128, 256>, cudaFuncAttributeMaxDynamicSharedMemorySize, 196608);
    cudaFuncSetAttribute(k_gemm<128, 64>,  cudaFuncAttributeMaxDynamicSharedMemorySize, 98304);
    cudaFuncSetAttribute(k_gemm<32, 64>,   cudaFuncAttributeMaxDynamicSharedMemorySize, 24576);

    int NB = (n + 1023) / 1024;
    int eg = (E + 255) / 256;
    int gb = (n + 127) / 128;
    int g_warp = (n * 32 + 255) / 256;   // one warp per node (layer1)
    int g_16   = (n * 16 + 255) / 256;   // 16 lanes per node (post D=128)
    int g_4    = (n * 4 + 255) / 256;    // 4 lanes per node (post D=32)

    // CSR build (degrees come free from rowptr diffs)
    cudaMemsetAsync(p_cnt, 0, n * sizeof(int));
    k_count<<<eg, 256>>>(ei, p_cnt, E);
    k_reduce<<<NB, 256>>>(p_cnt, p_bsum, n);
    k_spine<<<1, 1>>>(p_bsum, NB);
    k_scan<<<NB, 256>>>(p_cnt, p_bsum, p_rowptr, n);
    cudaMemcpyAsync(p_cursor, p_rowptr, n * sizeof(int), cudaMemcpyDeviceToDevice);
    k_fill<<<eg, 256>>>(ei, p_cursor, p_csrc, E);

    // layer 1 (2 -> 128): aggregate in dim 2, fused GEMM
    k_layer1<<<g_warp, 256>>>(x, p_rowptr, p_csrc, Wl1, bl1, Wr1, p_h, n);

    // layer 2 (128 -> 128)
    k_gemm<128, 256><<<gb, 256, 196608>>>(p_h, Wl2, Wr2, p_hl, p_hr, n);
    k_post<128><<<g_16, 256>>>(p_rowptr, p_csrc, p_hl, p_hr, bl2, p_h, n);

    // layer 3 (128 -> 32)
    k_gemm<128, 64><<<gb, 256, 98304>>>(p_h, Wl3, Wr3, p_hl, p_hr, n);
    k_post<32><<<g_4, 256>>>(p_rowptr, p_csrc, p_hl, p_hr, bl3, p_h, n);

    // layer 4 (32 -> 32)
    k_gemm<32, 64><<<gb, 256, 24576>>>(p_h, Wl4, Wr4, p_hl, p_hr, n);
    k_post<32><<<g_4, 256>>>(p_rowptr, p_csrc, p_hl, p_hr, bl4, p_h, n);

    // layer 5 (32 -> 32) + fused output head
    k_gemm<32, 64><<<gb, 256, 24576>>>(p_h, Wl5, Wr5, p_hl, p_hr, n);
    k_post_out<<<g_4, 256>>>(p_rowptr, p_csrc, p_hl, p_hr, bl5, Wo, bo, out, n);
}

// round 3
// speedup vs baseline: 2.3495x; 2.1559x over previous
#include <cuda_runtime.h>
#include <cuda_fp16.h>
#include <cstdint>

#define NN 100000
#define NE 1600000

// ---------------- scratch ----------------
__device__ __half g_h [NN * 128];   // node features fp16 (GEMM A operand)
__device__ __half g_hl[NN * 128];   // h @ Wl fp16 (gathered operand)
__device__ float  g_hr[NN * 128];   // h @ Wr fp32 (skip path, read once)
__device__ __half g_w2[128 * 256];  // packed fp16 [K][Wl|Wr]
__device__ __half g_w3[128 * 64];
__device__ __half g_w4[32 * 64];
__device__ __half g_w5[32 * 64];
__device__ int    g_cnt[NN];
__device__ int    g_rowptr[NN + 1];
__device__ int    g_cursor[NN];
__device__ int    g_csrc[NE];
__device__ int    g_bsum[256];

// ---------------- mma helpers ----------------
__device__ __forceinline__ uint32_t smem_u32(const void* p) {
    return (uint32_t)__cvta_generic_to_shared(p);
}
__device__ __forceinline__ void ldsm_x4(uint32_t& r0, uint32_t& r1, uint32_t& r2, uint32_t& r3, uint32_t a) {
    asm volatile("ldmatrix.sync.aligned.m8n8.x4.shared.b16 {%0,%1,%2,%3},[%4];"
                 : "=r"(r0), "=r"(r1), "=r"(r2), "=r"(r3) : "r"(a));
}
__device__ __forceinline__ void ldsm_x2t(uint32_t& r0, uint32_t& r1, uint32_t a) {
    asm volatile("ldmatrix.sync.aligned.m8n8.x2.trans.shared.b16 {%0,%1},[%2];"
                 : "=r"(r0), "=r"(r1) : "r"(a));
}
__device__ __forceinline__ void mma16816(float* c, uint32_t a0, uint32_t a1, uint32_t a2, uint32_t a3,
                                         uint32_t b0, uint32_t b1) {
    asm volatile("mma.sync.aligned.m16n8k16.row.col.f32.f16.f16.f32 "
                 "{%0,%1,%2,%3},{%4,%5,%6,%7},{%8,%9},{%0,%1,%2,%3};"
                 : "+f"(c[0]), "+f"(c[1]), "+f"(c[2]), "+f"(c[3])
                 : "r"(a0), "r"(a1), "r"(a2), "r"(a3), "r"(b0), "r"(b1));
}

// ---------------- CSR build ----------------
__global__ void k_count(const int* __restrict__ ei, int* __restrict__ cnt, int E) {
    int e = blockIdx.x * blockDim.x + threadIdx.x;
    if (e < E) atomicAdd(&cnt[ei[E + e]], 1);
}

__global__ void k_reduce(const int* __restrict__ cnt, int* __restrict__ bsum, int n) {
    __shared__ int ws[8];
    int base = blockIdx.x * 1024 + threadIdx.x * 4;
    int s = 0;
#pragma unroll
    for (int q = 0; q < 4; q++) { int idx = base + q; if (idx < n) s += cnt[idx]; }
#pragma unroll
    for (int d = 16; d; d >>= 1) s += __shfl_down_sync(0xffffffffu, s, d);
    if ((threadIdx.x & 31) == 0) ws[threadIdx.x >> 5] = s;
    __syncthreads();
    if (threadIdx.x == 0) {
        int t = 0;
#pragma unroll
        for (int i = 0; i < 8; i++) t += ws[i];
        bsum[blockIdx.x] = t;
    }
}

__global__ void k_spine(int* bsum, int nb) {
    if (blockIdx.x == 0 && threadIdx.x == 0) {
        int run = 0;
        for (int i = 0; i < nb; i++) { int t = bsum[i]; bsum[i] = run; run += t; }
    }
}

__global__ void k_scan(const int* __restrict__ cnt, const int* __restrict__ bofs,
                       int* __restrict__ rowptr, int n) {
    __shared__ int ws[8];
    int base = blockIdx.x * 1024 + threadIdx.x * 4;
    int c[4];
#pragma unroll
    for (int q = 0; q < 4; q++) { int idx = base + q; c[q] = (idx < n) ? cnt[idx] : 0; }
    int s1 = c[0], s2 = s1 + c[1], s3 = s2 + c[2], s4 = s3 + c[3];
    int lane = threadIdx.x & 31, w = threadIdx.x >> 5;
    int v = s4;
#pragma unroll
    for (int d = 1; d < 32; d <<= 1) {
        int u = __shfl_up_sync(0xffffffffu, v, d);
        if (lane >= d) v += u;
    }
    int texcl = v - s4;
    if (lane == 31) ws[w] = v;
    __syncthreads();
    if (threadIdx.x == 0) {
        int run = 0;
        for (int i = 0; i < 8; i++) { int t = ws[i]; ws[i] = run; run += t; }
    }
    __syncthreads();
    int ofs = bofs[blockIdx.x] + ws[w] + texcl;
    int sv[4] = {s1, s2, s3, s4};
#pragma unroll
    for (int q = 0; q < 4; q++) { int idx = base + q; if (idx < n) rowptr[idx + 1] = ofs + sv[q]; }
    if (blockIdx.x == 0 && threadIdx.x == 0) rowptr[0] = 0;
}

__global__ void k_fill(const int* __restrict__ ei, int* __restrict__ cursor,
                       int* __restrict__ csrc, int E) {
    int e = blockIdx.x * blockDim.x + threadIdx.x;
    if (e < E) {
        int s = ei[e], d = ei[E + e];
        int p = atomicAdd(&cursor[d], 1);
        csrc[p] = s;
    }
}

// ---------------- weight pack: fp32 Wl/Wr -> fp16 [K][Wl|Wr] (all 4 layers, 1 launch) ------
__global__ void k_pack(const float* Wl2, const float* Wr2, const float* Wl3, const float* Wr3,
                       const float* Wl4, const float* Wr4, const float* Wl5, const float* Wr5,
                       __half* w2, __half* w3, __half* w4, __half* w5) {
    int i = blockIdx.x * blockDim.x + threadIdx.x;
    // segment sizes: 32768, 8192, 2048, 2048
    if (i < 32768) {
        int k = i / 256, j = i % 256;
        float v = (j < 128) ? Wl2[k * 128 + j] : Wr2[k * 128 + j - 128];
        w2[i] = __float2half_rn(v);
    } else if (i < 40960) {
        int q = i - 32768;
        int k = q / 64, j = q % 64;
        float v = (j < 32) ? Wl3[k * 32 + j] : Wr3[k * 32 + j - 32];
        w3[q] = __float2half_rn(v);
    } else if (i < 43008) {
        int q = i - 40960;
        int k = q / 64, j = q % 64;
        float v = (j < 32) ? Wl4[k * 32 + j] : Wr4[k * 32 + j - 32];
        w4[q] = __float2half_rn(v);
    } else if (i < 45056) {
        int q = i - 43008;
        int k = q / 64, j = q % 64;
        float v = (j < 32) ? Wl5[k * 32 + j] : Wr5[k * 32 + j - 32];
        w5[q] = __float2half_rn(v);
    }
}

// ---------------- layer 1: mean-agg in dim 2, fused tiny GEMM (2->128), fp16 out ----------
__global__ void k_layer1(const float* __restrict__ x, const int* __restrict__ rowptr,
                         const int* __restrict__ csrc,
                         const float* __restrict__ Wl, const float* __restrict__ bl,
                         const float* __restrict__ Wr,
                         __half* __restrict__ hout, int n) {
    __shared__ float sWl[256], sWr[256], sbl[128];
    for (int i = threadIdx.x; i < 256; i += blockDim.x) { sWl[i] = Wl[i]; sWr[i] = Wr[i]; }
    for (int i = threadIdx.x; i < 128; i += blockDim.x) sbl[i] = bl[i];
    __syncthreads();
    int gw = (blockIdx.x * blockDim.x + threadIdx.x) >> 5;
    int lane = threadIdx.x & 31;
    if (gw >= n) return;
    int rs = rowptr[gw], re = rowptr[gw + 1];
    float ax = 0.f, ay = 0.f;
    for (int t = rs + lane; t < re; t += 32) {
        int s = csrc[t];
        float2 v = *(const float2*)&x[2 * s];
        ax += v.x; ay += v.y;
    }
#pragma unroll
    for (int d = 16; d; d >>= 1) {
        ax += __shfl_xor_sync(0xffffffffu, ax, d);
        ay += __shfl_xor_sync(0xffffffffu, ay, d);
    }
    float dv = (float)(re - rs);
    float inv = 1.0f / fmaxf(dv, 1.0f);
    ax *= inv; ay *= inv;
    float2 xv = *(const float2*)&x[2 * gw];
    int j = lane * 4;
    float o0 = fmaxf(ax * sWl[j + 0] + ay * sWl[128 + j + 0] + sbl[j + 0] + xv.x * sWr[j + 0] + xv.y * sWr[128 + j + 0], 0.f);
    float o1 = fmaxf(ax * sWl[j + 1] + ay * sWl[128 + j + 1] + sbl[j + 1] + xv.x * sWr[j + 1] + xv.y * sWr[128 + j + 1], 0.f);
    float o2 = fmaxf(ax * sWl[j + 2] + ay * sWl[128 + j + 2] + sbl[j + 2] + xv.x * sWr[j + 2] + xv.y * sWr[128 + j + 2], 0.f);
    float o3 = fmaxf(ax * sWl[j + 3] + ay * sWl[128 + j + 3] + sbl[j + 3] + xv.x * sWr[j + 3] + xv.y * sWr[128 + j + 3], 0.f);
    __half2 p0 = __floats2half2_rn(o0, o1);
    __half2 p1 = __floats2half2_rn(o2, o3);
    uint2 v;
    v.x = *(unsigned*)&p0; v.y = *(unsigned*)&p1;
    *(uint2*)&hout[gw * 128 + j] = v;
}

// ---------------- tensor-core GEMM: [Cl(fp16) | Cr(fp32)] = A[n,K] @ Wcat[K,2*COUT] --------
// Block: 128 rows. Warp grid 4 x (BN/WN); warp tile 32 x WN.
template <int K, int COUT, int WN>
__global__ void k_gemm_mma(const __half* __restrict__ A, const __half* __restrict__ W,
                           __half* __restrict__ Cl, float* __restrict__ Cr, int n) {
    constexpr int BN = 2 * COUT;
    constexpr int NWN = BN / WN;
    constexpr int NW = 4 * NWN;
    constexpr int THREADS = NW * 32;
    constexpr int LDA = K + 8;
    constexpr int LDB = BN + 8;
    constexpr int NFN = WN / 8;
    extern __shared__ __half sm[];
    __half* As = sm;               // [128][LDA]
    __half* Bs = sm + 128 * LDA;   // [K][LDB]
    int tid = threadIdx.x;
    int row0 = blockIdx.x * 128;

    // load W tile [K][BN]
    for (int i = tid; i < K * BN / 8; i += THREADS) {
        int f = i * 8;
        int k = f / BN, j = f % BN;
        *(uint4*)&Bs[k * LDB + j] = *(const uint4*)&W[f];
    }
    // load A tile [128][K]
    for (int i = tid; i < 128 * K / 8; i += THREADS) {
        int f = i * 8;
        int m = f / K, k = f % K;
        int row = row0 + m;
        uint4 v = make_uint4(0u, 0u, 0u, 0u);
        if (row < n) v = *(const uint4*)&A[row * K + k];
        *(uint4*)&As[m * LDA + k] = v;
    }
    __syncthreads();

    int wid = tid >> 5, lane = tid & 31;
    int wm = wid & 3, wn = wid >> 2;
    int m_base = wm * 32, n_base = wn * WN;

    float acc[2][NFN][4];
#pragma unroll
    for (int im = 0; im < 2; im++)
#pragma unroll
        for (int jn = 0; jn < NFN; jn++)
#pragma unroll
            for (int q = 0; q < 4; q++) acc[im][jn][q] = 0.f;

    int lr = lane & 15, lc = lane >> 4;
    uint32_t a_base0 = smem_u32(&As[(m_base + lr) * LDA]);
    uint32_t a_base1 = smem_u32(&As[(m_base + 16 + lr) * LDA]);
    uint32_t b_base = smem_u32(&Bs[lr * LDB + n_base]);

#pragma unroll
    for (int k0 = 0; k0 < K; k0 += 16) {
        uint32_t af[2][4];
        ldsm_x4(af[0][0], af[0][1], af[0][2], af[0][3], a_base0 + (k0 + lc * 8) * 2);
        ldsm_x4(af[1][0], af[1][1], af[1][2], af[1][3], a_base1 + (k0 + lc * 8) * 2);
        uint32_t bf[NFN][2];
#pragma unroll
        for (int jn = 0; jn < NFN; jn++)
            ldsm_x2t(bf[jn][0], bf[jn][1], b_base + (k0 * LDB + jn * 8) * 2);
#pragma unroll
        for (int im = 0; im < 2; im++)
#pragma unroll
            for (int jn = 0; jn < NFN; jn++)
                mma16816(acc[im][jn], af[im][0], af[im][1], af[im][2], af[im][3],
                         bf[jn][0], bf[jn][1]);
    }

    int quad = lane >> 2, t4 = lane & 3;
#pragma unroll
    for (int im = 0; im < 2; im++) {
#pragma unroll
        for (int jn = 0; jn < NFN; jn++) {
            int col = n_base + jn * 8 + t4 * 2;
            int r0 = row0 + m_base + im * 16 + quad;
            int r1 = r0 + 8;
            if (col < COUT) {
                if (r0 < n) {
                    __half2 h = __floats2half2_rn(acc[im][jn][0], acc[im][jn][1]);
                    *(__half2*)&Cl[r0 * COUT + col] = h;
                }
                if (r1 < n) {
                    __half2 h = __floats2half2_rn(acc[im][jn][2], acc[im][jn][3]);
                    *(__half2*)&Cl[r1 * COUT + col] = h;
                }
            } else {
                int c = col - COUT;
                if (r0 < n) *(float2*)&Cr[r0 * COUT + c] = make_float2(acc[im][jn][0], acc[im][jn][1]);
                if (r1 < n) *(float2*)&Cr[r1 * COUT + c] = make_float2(acc[im][jn][2], acc[im][jn][3]);
            }
        }
    }
}

// ---------------- post: h = relu(mean_agg(hl fp16) + bl + hr fp32) -> fp16 ------------------
template <int D>
__global__ void k_post(const int* __restrict__ rowptr, const int* __restrict__ csrc,
                       const __half* __restrict__ hl, const float* __restrict__ hr,
                       const float* __restrict__ bl, __half* __restrict__ hout, int n) {
    constexpr int LPN = D / 8;
    int tid = blockIdx.x * blockDim.x + threadIdx.x;
    int node = tid / LPN;
    int sub = tid % LPN;
    if (node >= n) return;
    int rs = rowptr[node], re = rowptr[node + 1];
    float a0 = 0.f, a1 = 0.f, a2 = 0.f, a3 = 0.f, a4 = 0.f, a5 = 0.f, a6 = 0.f, a7 = 0.f;
    int t = rs;
    for (; t + 1 < re; t += 2) {
        int s0 = csrc[t], s1 = csrc[t + 1];
        uint4 v0 = *(const uint4*)&hl[s0 * D + sub * 8];
        uint4 v1 = *(const uint4*)&hl[s1 * D + sub * 8];
        float2 f;
        f = __half22float2(*(__half2*)&v0.x); a0 += f.x; a1 += f.y;
        f = __half22float2(*(__half2*)&v0.y); a2 += f.x; a3 += f.y;
        f = __half22float2(*(__half2*)&v0.z); a4 += f.x; a5 += f.y;
        f = __half22float2(*(__half2*)&v0.w); a6 += f.x; a7 += f.y;
        f = __half22float2(*(__half2*)&v1.x); a0 += f.x; a1 += f.y;
        f = __half22float2(*(__half2*)&v1.y); a2 += f.x; a3 += f.y;
        f = __half22float2(*(__half2*)&v1.z); a4 += f.x; a5 += f.y;
        f = __half22float2(*(__half2*)&v1.w); a6 += f.x; a7 += f.y;
    }
    if (t < re) {
        int s0 = csrc[t];
        uint4 v0 = *(const uint4*)&hl[s0 * D + sub * 8];
        float2 f;
        f = __half22float2(*(__half2*)&v0.x); a0 += f.x; a1 += f.y;
        f = __half22float2(*(__half2*)&v0.y); a2 += f.x; a3 += f.y;
        f = __half22float2(*(__half2*)&v0.z); a4 += f.x; a5 += f.y;
        f = __half22float2(*(__half2*)&v0.w); a6 += f.x; a7 += f.y;
    }
    float dv = (float)(re - rs);
    float inv = 1.0f / fmaxf(dv, 1.0f);
    float4 r0 = *(const float4*)&hr[node * D + sub * 8];
    float4 r1 = *(const float4*)&hr[node * D + sub * 8 + 4];
    float4 b0 = *(const float4*)&bl[sub * 8];
    float4 b1 = *(const float4*)&bl[sub * 8 + 4];
    float o0 = fmaxf(a0 * inv + b0.x + r0.x, 0.f);
    float o1 = fmaxf(a1 * inv + b0.y + r0.y, 0.f);
    float o2 = fmaxf(a2 * inv + b0.z + r0.z, 0.f);
    float o3 = fmaxf(a3 * inv + b0.w + r0.w, 0.f);
    float o4 = fmaxf(a4 * inv + b1.x + r1.x, 0.f);
    float o5 = fmaxf(a5 * inv + b1.y + r1.y, 0.f);
    float o6 = fmaxf(a6 * inv + b1.z + r1.z, 0.f);
    float o7 = fmaxf(a7 * inv + b1.w + r1.w, 0.f);
    __half2 p0 = __floats2half2_rn(o0, o1);
    __half2 p1 = __floats2half2_rn(o2, o3);
    __half2 p2 = __floats2half2_rn(o4, o5);
    __half2 p3 = __floats2half2_rn(o6, o7);
    uint4 ov;
    ov.x = *(unsigned*)&p0; ov.y = *(unsigned*)&p1;
    ov.z = *(unsigned*)&p2; ov.w = *(unsigned*)&p3;
    *(uint4*)&hout[node * D + sub * 8] = ov;
}

// ---------------- layer 5 post fused with output head ----------------
__global__ void k_post_out(const int* __restrict__ rowptr, const int* __restrict__ csrc,
                           const __half* __restrict__ hl, const float* __restrict__ hr,
                           const float* __restrict__ bl,
                           const float* __restrict__ Wo, const float* __restrict__ bo,
                           float* __restrict__ out, int n) {
    constexpr int D = 32;
    constexpr int LPN = 4;
    int tid = blockIdx.x * blockDim.x + threadIdx.x;
    int node = tid / LPN;
    int sub = tid % LPN;
    if (node >= n) return;
    int rs = rowptr[node], re = rowptr[node + 1];
    float a0 = 0.f, a1 = 0.f, a2 = 0.f, a3 = 0.f, a4 = 0.f, a5 = 0.f, a6 = 0.f, a7 = 0.f;
    int t = rs;
    for (; t + 1 < re; t += 2) {
        int s0 = csrc[t], s1 = csrc[t + 1];
        uint4 v0 = *(const uint4*)&hl[s0 * D + sub * 8];
        uint4 v1 = *(const uint4*)&hl[s1 * D + sub * 8];
        float2 f;
        f = __half22float2(*(__half2*)&v0.x); a0 += f.x; a1 += f.y;
        f = __half22float2(*(__half2*)&v0.y); a2 += f.x; a3 += f.y;
        f = __half22float2(*(__half2*)&v0.z); a4 += f.x; a5 += f.y;
        f = __half22float2(*(__half2*)&v0.w); a6 += f.x; a7 += f.y;
        f = __half22float2(*(__half2*)&v1.x); a0 += f.x; a1 += f.y;
        f = __half22float2(*(__half2*)&v1.y); a2 += f.x; a3 += f.y;
        f = __half22float2(*(__half2*)&v1.z); a4 += f.x; a5 += f.y;
        f = __half22float2(*(__half2*)&v1.w); a6 += f.x; a7 += f.y;
    }
    if (t < re) {
        int s0 = csrc[t];
        uint4 v0 = *(const uint4*)&hl[s0 * D + sub * 8];
        float2 f;
        f = __half22float2(*(__half2*)&v0.x); a0 += f.x; a1 += f.y;
        f = __half22float2(*(__half2*)&v0.y); a2 += f.x; a3 += f.y;
        f = __half22float2(*(__half2*)&v0.z); a4 += f.x; a5 += f.y;
        f = __half22float2(*(__half2*)&v0.w); a6 += f.x; a7 += f.y;
    }
    float dv = (float)(re - rs);
    float inv = 1.0f / fmaxf(dv, 1.0f);
    float4 r0 = *(const float4*)&hr[node * D + sub * 8];
    float4 r1 = *(const float4*)&hr[node * D + sub * 8 + 4];
    float4 b0 = *(const float4*)&bl[sub * 8];
    float4 b1 = *(const float4*)&bl[sub * 8 + 4];
    float4 w0 = *(const float4*)&Wo[sub * 8];
    float4 w1 = *(const float4*)&Wo[sub * 8 + 4];
    float s = 0.f;
    s += fmaxf(a0 * inv + b0.x + r0.x, 0.f) * w0.x;
    s += fmaxf(a1 * inv + b0.y + r0.y, 0.f) * w0.y;
    s += fmaxf(a2 * inv + b0.z + r0.z, 0.f) * w0.z;
    s += fmaxf(a3 * inv + b0.w + r0.w, 0.f) * w0.w;
    s += fmaxf(a4 * inv + b1.x + r1.x, 0.f) * w1.x;
    s += fmaxf(a5 * inv + b1.y + r1.y, 0.f) * w1.y;
    s += fmaxf(a6 * inv + b1.z + r1.z, 0.f) * w1.z;
    s += fmaxf(a7 * inv + b1.w + r1.w, 0.f) * w1.w;
    s += __shfl_xor_sync(0xffffffffu, s, 1);
    s += __shfl_xor_sync(0xffffffffu, s, 2);
    if (sub == 0) out[node] = s + bo[0];
}

// ---------------- launch ----------------
extern "C" void kernel_launch(void* const* d_in, const int* in_sizes, int n_in,
                              void* d_out, int out_size) {
    const float* x   = (const float*)d_in[0];
    const int*   ei  = (const int*)d_in[1];
    const float* Wl1 = (const float*)d_in[3];
    const float* bl1 = (const float*)d_in[4];
    const float* Wr1 = (const float*)d_in[5];
    const float* Wl2 = (const float*)d_in[6];
    const float* bl2 = (const float*)d_in[7];
    const float* Wr2 = (const float*)d_in[8];
    const float* Wl3 = (const float*)d_in[9];
    const float* bl3 = (const float*)d_in[10];
    const float* Wr3 = (const float*)d_in[11];
    const float* Wl4 = (const float*)d_in[12];
    const float* bl4 = (const float*)d_in[13];
    const float* Wr4 = (const float*)d_in[14];
    const float* Wl5 = (const float*)d_in[15];
    const float* bl5 = (const float*)d_in[16];
    const float* Wr5 = (const float*)d_in[17];
    const float* Wo  = (const float*)d_in[18];
    const float* bo  = (const float*)d_in[19];
    float* out = (float*)d_out;

    int n = in_sizes[0] / 2;
    int E = in_sizes[1] / 2;

    __half *p_h, *p_hl, *p_w2, *p_w3, *p_w4, *p_w5;
    float* p_hr;
    int *p_cnt, *p_rowptr, *p_cursor, *p_csrc, *p_bsum;
    cudaGetSymbolAddress((void**)&p_h, g_h);
    cudaGetSymbolAddress((void**)&p_hl, g_hl);
    cudaGetSymbolAddress((void**)&p_hr, g_hr);
    cudaGetSymbolAddress((void**)&p_w2, g_w2);
    cudaGetSymbolAddress((void**)&p_w3, g_w3);
    cudaGetSymbolAddress((void**)&p_w4, g_w4);
    cudaGetSymbolAddress((void**)&p_w5, g_w5);
    cudaGetSymbolAddress((void**)&p_cnt, g_cnt);
    cudaGetSymbolAddress((void**)&p_rowptr, g_rowptr);
    cudaGetSymbolAddress((void**)&p_cursor, g_cursor);
    cudaGetSymbolAddress((void**)&p_csrc, g_csrc);
    cudaGetSymbolAddress((void**)&p_bsum, g_bsum);

    // smem sizes: L2 102400, L3 53248, L4/5 14848
    cudaFuncSetAttribute(k_gemm_mma<128, 128, 64>, cudaFuncAttributeMaxDynamicSharedMemorySize, 102400);
    cudaFuncSetAttribute(k_gemm_mma<128, 32, 32>,  cudaFuncAttributeMaxDynamicSharedMemorySize, 53248);
    cudaFuncSetAttribute(k_gemm_mma<32, 32, 32>,   cudaFuncAttributeMaxDynamicSharedMemorySize, 14848);

    int NB = (n + 1023) / 1024;
    int eg = (E + 255) / 256;
    int gb = (n + 127) / 128;
    int g_warp = (n * 32 + 255) / 256;
    int g_16   = (n * 16 + 255) / 256;
    int g_4    = (n * 4 + 255) / 256;

    // weight pack (independent, front of pipeline)
    k_pack<<<(45056 + 255) / 256, 256>>>(Wl2, Wr2, Wl3, Wr3, Wl4, Wr4, Wl5, Wr5,
                                         p_w2, p_w3, p_w4, p_w5);

    // CSR build
    cudaMemsetAsync(p_cnt, 0, n * sizeof(int));
    k_count<<<eg, 256>>>(ei, p_cnt, E);
    k_reduce<<<NB, 256>>>(p_cnt, p_bsum, n);
    k_spine<<<1, 1>>>(p_bsum, NB);
    k_scan<<<NB, 256>>>(p_cnt, p_bsum, p_rowptr, n);
    cudaMemcpyAsync(p_cursor, p_rowptr, n * sizeof(int), cudaMemcpyDeviceToDevice);
    k_fill<<<eg, 256>>>(ei, p_cursor, p_csrc, E);

    // layer 1 (2 -> 128)
    k_layer1<<<g_warp, 256>>>(x, p_rowptr, p_csrc, Wl1, bl1, Wr1, p_h, n);

    // layer 2 (128 -> 128): tensor-core GEMM + post
    k_gemm_mma<128, 128, 64><<<gb, 512, 102400>>>(p_h, p_w2, p_hl, p_hr, n);
    k_post<128><<<g_16, 256>>>(p_rowptr, p_csrc, p_hl, p_hr, bl2, p_h, n);

    // layer 3 (128 -> 32)
    k_gemm_mma<128, 32, 32><<<gb, 256, 53248>>>(p_h, p_w3, p_hl, p_hr, n);
    k_post<32><<<g_4, 256>>>(p_rowptr, p_csrc, p_hl, p_hr, bl3, p_h, n);

    // layer 4 (32 -> 32)
    k_gemm_mma<32, 32, 32><<<gb, 256, 14848>>>(p_h, p_w4, p_hl, p_hr, n);
    k_post<32><<<g_4, 256>>>(p_rowptr, p_csrc, p_hl, p_hr, bl4, p_h, n);

    // layer 5 (32 -> 32) + fused output head
    k_gemm_mma<32, 32, 32><<<gb, 256, 14848>>>(p_h, p_w5, p_hl, p_hr, n);
    k_post_out<<<g_4, 256>>>(p_rowptr, p_csrc, p_hl, p_hr, bl5, Wo, bo, out, n);
}

// round 4
// speedup vs baseline: 2.3526x; 1.0013x over previous
#include <cuda_runtime.h>
#include <cuda_fp16.h>
#include <cstdint>

#define NN 100000
#define NE 1600000

// ---------------- scratch ----------------
__device__ __half g_h [NN * 128];   // node features fp16 (GEMM A operand)
__device__ __half g_hl[NN * 128];   // h @ Wl fp16 (gathered operand)
__device__ float  g_hr[NN * 128];   // h @ Wr fp32 (skip path, read once)
__device__ __half g_w2[128 * 256];  // packed fp16 [K][Wl|Wr]
__device__ __half g_w3[128 * 64];
__device__ __half g_w4[32 * 64];
__device__ __half g_w5[32 * 64];
__device__ int    g_cnt[NN];
__device__ int    g_rowptr[NN + 1];
__device__ int    g_cursor[NN];
__device__ int    g_csrc[NE];
__device__ int    g_bsum[256];

// ---------------- mma helpers ----------------
__device__ __forceinline__ uint32_t smem_u32(const void* p) {
    return (uint32_t)__cvta_generic_to_shared(p);
}
__device__ __forceinline__ void ldsm_x4(uint32_t& r0, uint32_t& r1, uint32_t& r2, uint32_t& r3, uint32_t a) {
    asm volatile("ldmatrix.sync.aligned.m8n8.x4.shared.b16 {%0,%1,%2,%3},[%4];"
                 : "=r"(r0), "=r"(r1), "=r"(r2), "=r"(r3) : "r"(a));
}
__device__ __forceinline__ void ldsm_x2t(uint32_t& r0, uint32_t& r1, uint32_t a) {
    asm volatile("ldmatrix.sync.aligned.m8n8.x2.trans.shared.b16 {%0,%1},[%2];"
                 : "=r"(r0), "=r"(r1) : "r"(a));
}
__device__ __forceinline__ void mma16816(float* c, uint32_t a0, uint32_t a1, uint32_t a2, uint32_t a3,
                                         uint32_t b0, uint32_t b1) {
    asm volatile("mma.sync.aligned.m16n8k16.row.col.f32.f16.f16.f32 "
                 "{%0,%1,%2,%3},{%4,%5,%6,%7},{%8,%9},{%0,%1,%2,%3};"
                 : "+f"(c[0]), "+f"(c[1]), "+f"(c[2]), "+f"(c[3])
                 : "r"(a0), "r"(a1), "r"(a2), "r"(a3), "r"(b0), "r"(b1));
}

// ---------------- CSR build ----------------
__global__ void k_count(const int* __restrict__ ei, int* __restrict__ cnt, int E) {
    int e = blockIdx.x * blockDim.x + threadIdx.x;
    if (e < E) atomicAdd(&cnt[ei[E + e]], 1);
}

__global__ void k_reduce(const int* __restrict__ cnt, int* __restrict__ bsum, int n) {
    __shared__ int ws[8];
    int base = blockIdx.x * 1024 + threadIdx.x * 4;
    int s = 0;
#pragma unroll
    for (int q = 0; q < 4; q++) { int idx = base + q; if (idx < n) s += cnt[idx]; }
#pragma unroll
    for (int d = 16; d; d >>= 1) s += __shfl_down_sync(0xffffffffu, s, d);
    if ((threadIdx.x & 31) == 0) ws[threadIdx.x >> 5] = s;
    __syncthreads();
    if (threadIdx.x == 0) {
        int t = 0;
#pragma unroll
        for (int i = 0; i < 8; i++) t += ws[i];
        bsum[blockIdx.x] = t;
    }
}

// parallel exclusive scan over <=128 block sums (1 block, 128 threads)
__global__ void k_spine(int* bsum, int nb) {
    __shared__ int ws[4];
    int tid = threadIdx.x;
    int v = (tid < nb) ? bsum[tid] : 0;
    int lane = tid & 31, w = tid >> 5;
    int s = v;
#pragma unroll
    for (int d = 1; d < 32; d <<= 1) {
        int u = __shfl_up_sync(0xffffffffu, s, d);
        if (lane >= d) s += u;
    }
    if (lane == 31) ws[w] = s;
    __syncthreads();
    if (tid == 0) {
        int run = 0;
#pragma unroll
        for (int i = 0; i < 4; i++) { int t = ws[i]; ws[i] = run; run += t; }
    }
    __syncthreads();
    if (tid < nb) bsum[tid] = s - v + ws[w];
}

__global__ void k_scan(const int* __restrict__ cnt, const int* __restrict__ bofs,
                       int* __restrict__ rowptr, int* __restrict__ cursor, int n) {
    __shared__ int ws[8];
    int base = blockIdx.x * 1024 + threadIdx.x * 4;
    int c[4];
#pragma unroll
    for (int q = 0; q < 4; q++) { int idx = base + q; c[q] = (idx < n) ? cnt[idx] : 0; }
    int s1 = c[0], s2 = s1 + c[1], s3 = s2 + c[2], s4 = s3 + c[3];
    int lane = threadIdx.x & 31, w = threadIdx.x >> 5;
    int v = s4;
#pragma unroll
    for (int d = 1; d < 32; d <<= 1) {
        int u = __shfl_up_sync(0xffffffffu, v, d);
        if (lane >= d) v += u;
    }
    int texcl = v - s4;
    if (lane == 31) ws[w] = v;
    __syncthreads();
    if (threadIdx.x == 0) {
        int run = 0;
        for (int i = 0; i < 8; i++) { int t = ws[i]; ws[i] = run; run += t; }
    }
    __syncthreads();
    int ofs = bofs[blockIdx.x] + ws[w] + texcl;
    int sv[4] = {s1, s2, s3, s4};
#pragma unroll
    for (int q = 0; q < 4; q++) {
        int idx = base + q;
        if (idx < n) {
            int val = ofs + sv[q];
            rowptr[idx + 1] = val;
            // exclusive value for idx is ofs + sv[q] - c[q]
            cursor[idx] = val - c[q];
        }
    }
    if (blockIdx.x == 0 && threadIdx.x == 0) rowptr[0] = 0;
}

__global__ void k_fill(const int* __restrict__ ei, int* __restrict__ cursor,
                       int* __restrict__ csrc, int E) {
    int e = blockIdx.x * blockDim.x + threadIdx.x;
    if (e < E) {
        int s = ei[e], d = ei[E + e];
        int p = atomicAdd(&cursor[d], 1);
        csrc[p] = s;
    }
}

// ---------------- weight pack ----------------
__global__ void k_pack(const float* Wl2, const float* Wr2, const float* Wl3, const float* Wr3,
                       const float* Wl4, const float* Wr4, const float* Wl5, const float* Wr5,
                       __half* w2, __half* w3, __half* w4, __half* w5) {
    int i = blockIdx.x * blockDim.x + threadIdx.x;
    if (i < 32768) {
        int k = i / 256, j = i % 256;
        float v = (j < 128) ? Wl2[k * 128 + j] : Wr2[k * 128 + j - 128];
        w2[i] = __float2half_rn(v);
    } else if (i < 40960) {
        int q = i - 32768;
        int k = q / 64, j = q % 64;
        float v = (j < 32) ? Wl3[k * 32 + j] : Wr3[k * 32 + j - 32];
        w3[q] = __float2half_rn(v);
    } else if (i < 43008) {
        int q = i - 40960;
        int k = q / 64, j = q % 64;
        float v = (j < 32) ? Wl4[k * 32 + j] : Wr4[k * 32 + j - 32];
        w4[q] = __float2half_rn(v);
    } else if (i < 45056) {
        int q = i - 43008;
        int k = q / 64, j = q % 64;
        float v = (j < 32) ? Wl5[k * 32 + j] : Wr5[k * 32 + j - 32];
        w5[q] = __float2half_rn(v);
    }
}

// ---------------- layer 1 ----------------
__global__ void k_layer1(const float* __restrict__ x, const int* __restrict__ rowptr,
                         const int* __restrict__ csrc,
                         const float* __restrict__ Wl, const float* __restrict__ bl,
                         const float* __restrict__ Wr,
                         __half* __restrict__ hout, int n) {
    __shared__ float sWl[256], sWr[256], sbl[128];
    for (int i = threadIdx.x; i < 256; i += blockDim.x) { sWl[i] = Wl[i]; sWr[i] = Wr[i]; }
    for (int i = threadIdx.x; i < 128; i += blockDim.x) sbl[i] = bl[i];
    __syncthreads();
    int gw = (blockIdx.x * blockDim.x + threadIdx.x) >> 5;
    int lane = threadIdx.x & 31;
    if (gw >= n) return;
    int rs = rowptr[gw], re = rowptr[gw + 1];
    float ax = 0.f, ay = 0.f;
    for (int t = rs + lane; t < re; t += 32) {
        int s = csrc[t];
        float2 v = *(const float2*)&x[2 * s];
        ax += v.x; ay += v.y;
    }
#pragma unroll
    for (int d = 16; d; d >>= 1) {
        ax += __shfl_xor_sync(0xffffffffu, ax, d);
        ay += __shfl_xor_sync(0xffffffffu, ay, d);
    }
    float dv = (float)(re - rs);
    float inv = 1.0f / fmaxf(dv, 1.0f);
    ax *= inv; ay *= inv;
    float2 xv = *(const float2*)&x[2 * gw];
    int j = lane * 4;
    float o0 = fmaxf(ax * sWl[j + 0] + ay * sWl[128 + j + 0] + sbl[j + 0] + xv.x * sWr[j + 0] + xv.y * sWr[128 + j + 0], 0.f);
    float o1 = fmaxf(ax * sWl[j + 1] + ay * sWl[128 + j + 1] + sbl[j + 1] + xv.x * sWr[j + 1] + xv.y * sWr[128 + j + 1], 0.f);
    float o2 = fmaxf(ax * sWl[j + 2] + ay * sWl[128 + j + 2] + sbl[j + 2] + xv.x * sWr[j + 2] + xv.y * sWr[128 + j + 2], 0.f);
    float o3 = fmaxf(ax * sWl[j + 3] + ay * sWl[128 + j + 3] + sbl[j + 3] + xv.x * sWr[j + 3] + xv.y * sWr[128 + j + 3], 0.f);
    __half2 p0 = __floats2half2_rn(o0, o1);
    __half2 p1 = __floats2half2_rn(o2, o3);
    uint2 v;
    v.x = *(unsigned*)&p0; v.y = *(unsigned*)&p1;
    *(uint2*)&hout[gw * 128 + j] = v;
}

// ---------------- tensor-core GEMM ----------------
template <int K, int COUT, int WN>
__global__ void k_gemm_mma(const __half* __restrict__ A, const __half* __restrict__ W,
                           __half* __restrict__ Cl, float* __restrict__ Cr, int n) {
    constexpr int BN = 2 * COUT;
    constexpr int NWN = BN / WN;
    constexpr int NW = 4 * NWN;
    constexpr int THREADS = NW * 32;
    constexpr int LDA = K + 8;
    constexpr int LDB = BN + 8;
    constexpr int NFN = WN / 8;
    extern __shared__ __half sm[];
    __half* As = sm;
    __half* Bs = sm + 128 * LDA;
    int tid = threadIdx.x;
    int row0 = blockIdx.x * 128;

    for (int i = tid; i < K * BN / 8; i += THREADS) {
        int f = i * 8;
        int k = f / BN, j = f % BN;
        *(uint4*)&Bs[k * LDB + j] = *(const uint4*)&W[f];
    }
    for (int i = tid; i < 128 * K / 8; i += THREADS) {
        int f = i * 8;
        int m = f / K, k = f % K;
        int row = row0 + m;
        uint4 v = make_uint4(0u, 0u, 0u, 0u);
        if (row < n) v = *(const uint4*)&A[row * K + k];
        *(uint4*)&As[m * LDA + k] = v;
    }
    __syncthreads();

    int wid = tid >> 5, lane = tid & 31;
    int wm = wid & 3, wn = wid >> 2;
    int m_base = wm * 32, n_base = wn * WN;

    float acc[2][NFN][4];
#pragma unroll
    for (int im = 0; im < 2; im++)
#pragma unroll
        for (int jn = 0; jn < NFN; jn++)
#pragma unroll
            for (int q = 0; q < 4; q++) acc[im][jn][q] = 0.f;

    int lr = lane & 15, lc = lane >> 4;
    uint32_t a_base0 = smem_u32(&As[(m_base + lr) * LDA]);
    uint32_t a_base1 = smem_u32(&As[(m_base + 16 + lr) * LDA]);
    uint32_t b_base = smem_u32(&Bs[lr * LDB + n_base]);

#pragma unroll
    for (int k0 = 0; k0 < K; k0 += 16) {
        uint32_t af[2][4];
        ldsm_x4(af[0][0], af[0][1], af[0][2], af[0][3], a_base0 + (k0 + lc * 8) * 2);
        ldsm_x4(af[1][0], af[1][1], af[1][2], af[1][3], a_base1 + (k0 + lc * 8) * 2);
        uint32_t bf[NFN][2];
#pragma unroll
        for (int jn = 0; jn < NFN; jn++)
            ldsm_x2t(bf[jn][0], bf[jn][1], b_base + (k0 * LDB + jn * 8) * 2);
#pragma unroll
        for (int im = 0; im < 2; im++)
#pragma unroll
            for (int jn = 0; jn < NFN; jn++)
                mma16816(acc[im][jn], af[im][0], af[im][1], af[im][2], af[im][3],
                         bf[jn][0], bf[jn][1]);
    }

    int quad = lane >> 2, t4 = lane & 3;
#pragma unroll
    for (int im = 0; im < 2; im++) {
#pragma unroll
        for (int jn = 0; jn < NFN; jn++) {
            int col = n_base + jn * 8 + t4 * 2;
            int r0 = row0 + m_base + im * 16 + quad;
            int r1 = r0 + 8;
            if (col < COUT) {
                if (r0 < n) {
                    __half2 h = __floats2half2_rn(acc[im][jn][0], acc[im][jn][1]);
                    *(__half2*)&Cl[r0 * COUT + col] = h;
                }
                if (r1 < n) {
                    __half2 h = __floats2half2_rn(acc[im][jn][2], acc[im][jn][3]);
                    *(__half2*)&Cl[r1 * COUT + col] = h;
                }
            } else {
                int c = col - COUT;
                if (r0 < n) *(float2*)&Cr[r0 * COUT + c] = make_float2(acc[im][jn][0], acc[im][jn][1]);
                if (r1 < n) *(float2*)&Cr[r1 * COUT + c] = make_float2(acc[im][jn][2], acc[im][jn][3]);
            }
        }
    }
}

// ---------------- post: unroll-4 gather, fp16 accumulate-in-fp32 ----------------
#define ACC8(v)                                              \
    do {                                                     \
        float2 _f;                                           \
        _f = __half22float2(*(__half2*)&(v).x); a0 += _f.x; a1 += _f.y; \
        _f = __half22float2(*(__half2*)&(v).y); a2 += _f.x; a3 += _f.y; \
        _f = __half22float2(*(__half2*)&(v).z); a4 += _f.x; a5 += _f.y; \
        _f = __half22float2(*(__half2*)&(v).w); a6 += _f.x; a7 += _f.y; \
    } while (0)

template <int D>
__global__ void k_post(const int* __restrict__ rowptr, const int* __restrict__ csrc,
                       const __half* __restrict__ hl, const float* __restrict__ hr,
                       const float* __restrict__ bl, __half* __restrict__ hout, int n) {
    constexpr int LPN = D / 8;
    int tid = blockIdx.x * blockDim.x + threadIdx.x;
    int node = tid / LPN;
    int sub = tid % LPN;
    if (node >= n) return;
    int rs = rowptr[node], re = rowptr[node + 1];
    float a0 = 0.f, a1 = 0.f, a2 = 0.f, a3 = 0.f, a4 = 0.f, a5 = 0.f, a6 = 0.f, a7 = 0.f;
    int t = rs;
    for (; t + 3 < re; t += 4) {
        int s0 = csrc[t], s1 = csrc[t + 1], s2 = csrc[t + 2], s3 = csrc[t + 3];
        uint4 v0 = *(const uint4*)&hl[s0 * D + sub * 8];
        uint4 v1 = *(const uint4*)&hl[s1 * D + sub * 8];
        uint4 v2 = *(const uint4*)&hl[s2 * D + sub * 8];
        uint4 v3 = *(const uint4*)&hl[s3 * D + sub * 8];
        ACC8(v0); ACC8(v1); ACC8(v2); ACC8(v3);
    }
    for (; t < re; t++) {
        int s0 = csrc[t];
        uint4 v0 = *(const uint4*)&hl[s0 * D + sub * 8];
        ACC8(v0);
    }
    float dv = (float)(re - rs);
    float inv = 1.0f / fmaxf(dv, 1.0f);
    float4 r0 = *(const float4*)&hr[node * D + sub * 8];
    float4 r1 = *(const float4*)&hr[node * D + sub * 8 + 4];
    float4 b0 = *(const float4*)&bl[sub * 8];
    float4 b1 = *(const float4*)&bl[sub * 8 + 4];
    float o0 = fmaxf(a0 * inv + b0.x + r0.x, 0.f);
    float o1 = fmaxf(a1 * inv + b0.y + r0.y, 0.f);
    float o2 = fmaxf(a2 * inv + b0.z + r0.z, 0.f);
    float o3 = fmaxf(a3 * inv + b0.w + r0.w, 0.f);
    float o4 = fmaxf(a4 * inv + b1.x + r1.x, 0.f);
    float o5 = fmaxf(a5 * inv + b1.y + r1.y, 0.f);
    float o6 = fmaxf(a6 * inv + b1.z + r1.z, 0.f);
    float o7 = fmaxf(a7 * inv + b1.w + r1.w, 0.f);
    __half2 p0 = __floats2half2_rn(o0, o1);
    __half2 p1 = __floats2half2_rn(o2, o3);
    __half2 p2 = __floats2half2_rn(o4, o5);
    __half2 p3 = __floats2half2_rn(o6, o7);
    uint4 ov;
    ov.x = *(unsigned*)&p0; ov.y = *(unsigned*)&p1;
    ov.z = *(unsigned*)&p2; ov.w = *(unsigned*)&p3;
    *(uint4*)&hout[node * D + sub * 8] = ov;
}

// ---------------- layer 5 post fused with output head ----------------
__global__ void k_post_out(const int* __restrict__ rowptr, const int* __restrict__ csrc,
                           const __half* __restrict__ hl, const float* __restrict__ hr,
                           const float* __restrict__ bl,
                           const float* __restrict__ Wo, const float* __restrict__ bo,
                           float* __restrict__ out, int n) {
    constexpr int D = 32;
    constexpr int LPN = 4;
    int tid = blockIdx.x * blockDim.x + threadIdx.x;
    int node = tid / LPN;
    int sub = tid % LPN;
    if (node >= n) return;
    int rs = rowptr[node], re = rowptr[node + 1];
    float a0 = 0.f, a1 = 0.f, a2 = 0.f, a3 = 0.f, a4 = 0.f, a5 = 0.f, a6 = 0.f, a7 = 0.f;
    int t = rs;
    for (; t + 3 < re; t += 4) {
        int s0 = csrc[t], s1 = csrc[t + 1], s2 = csrc[t + 2], s3 = csrc[t + 3];
        uint4 v0 = *(const uint4*)&hl[s0 * D + sub * 8];
        uint4 v1 = *(const uint4*)&hl[s1 * D + sub * 8];
        uint4 v2 = *(const uint4*)&hl[s2 * D + sub * 8];
        uint4 v3 = *(const uint4*)&hl[s3 * D + sub * 8];
        ACC8(v0); ACC8(v1); ACC8(v2); ACC8(v3);
    }
    for (; t < re; t++) {
        int s0 = csrc[t];
        uint4 v0 = *(const uint4*)&hl[s0 * D + sub * 8];
        ACC8(v0);
    }
    float dv = (float)(re - rs);
    float inv = 1.0f / fmaxf(dv, 1.0f);
    float4 r0 = *(const float4*)&hr[node * D + sub * 8];
    float4 r1 = *(const float4*)&hr[node * D + sub * 8 + 4];
    float4 b0 = *(const float4*)&bl[sub * 8];
    float4 b1 = *(const float4*)&bl[sub * 8 + 4];
    float4 w0 = *(const float4*)&Wo[sub * 8];
    float4 w1 = *(const float4*)&Wo[sub * 8 + 4];
    float s = 0.f;
    s += fmaxf(a0 * inv + b0.x + r0.x, 0.f) * w0.x;
    s += fmaxf(a1 * inv + b0.y + r0.y, 0.f) * w0.y;
    s += fmaxf(a2 * inv + b0.z + r0.z, 0.f) * w0.z;
    s += fmaxf(a3 * inv + b0.w + r0.w, 0.f) * w0.w;
    s += fmaxf(a4 * inv + b1.x + r1.x, 0.f) * w1.x;
    s += fmaxf(a5 * inv + b1.y + r1.y, 0.f) * w1.y;
    s += fmaxf(a6 * inv + b1.z + r1.z, 0.f) * w1.z;
    s += fmaxf(a7 * inv + b1.w + r1.w, 0.f) * w1.w;
    s += __shfl_xor_sync(0xffffffffu, s, 1);
    s += __shfl_xor_sync(0xffffffffu, s, 2);
    if (sub == 0) out[node] = s + bo[0];
}

// ---------------- launch ----------------
extern "C" void kernel_launch(void* const* d_in, const int* in_sizes, int n_in,
                              void* d_out, int out_size) {
    const float* x   = (const float*)d_in[0];
    const int*   ei  = (const int*)d_in[1];
    const float* Wl1 = (const float*)d_in[3];
    const float* bl1 = (const float*)d_in[4];
    const float* Wr1 = (const float*)d_in[5];
    const float* Wl2 = (const float*)d_in[6];
    const float* bl2 = (const float*)d_in[7];
    const float* Wr2 = (const float*)d_in[8];
    const float* Wl3 = (const float*)d_in[9];
    const float* bl3 = (const float*)d_in[10];
    const float* Wr3 = (const float*)d_in[11];
    const float* Wl4 = (const float*)d_in[12];
    const float* bl4 = (const float*)d_in[13];
    const float* Wr4 = (const float*)d_in[14];
    const float* Wl5 = (const float*)d_in[15];
    const float* bl5 = (const float*)d_in[16];
    const float* Wr5 = (const float*)d_in[17];
    const float* Wo  = (const float*)d_in[18];
    const float* bo  = (const float*)d_in[19];
    float* out = (float*)d_out;

    int n = in_sizes[0] / 2;
    int E = in_sizes[1] / 2;

    __half *p_h, *p_hl, *p_w2, *p_w3, *p_w4, *p_w5;
    float* p_hr;
    int *p_cnt, *p_rowptr, *p_cursor, *p_csrc, *p_bsum;
    cudaGetSymbolAddress((void**)&p_h, g_h);
    cudaGetSymbolAddress((void**)&p_hl, g_hl);
    cudaGetSymbolAddress((void**)&p_hr, g_hr);
    cudaGetSymbolAddress((void**)&p_w2, g_w2);
    cudaGetSymbolAddress((void**)&p_w3, g_w3);
    cudaGetSymbolAddress((void**)&p_w4, g_w4);
    cudaGetSymbolAddress((void**)&p_w5, g_w5);
    cudaGetSymbolAddress((void**)&p_cnt, g_cnt);
    cudaGetSymbolAddress((void**)&p_rowptr, g_rowptr);
    cudaGetSymbolAddress((void**)&p_cursor, g_cursor);
    cudaGetSymbolAddress((void**)&p_csrc, g_csrc);
    cudaGetSymbolAddress((void**)&p_bsum, g_bsum);

    cudaFuncSetAttribute(k_gemm_mma<128, 128, 64>, cudaFuncAttributeMaxDynamicSharedMemorySize, 102400);
    cudaFuncSetAttribute(k_gemm_mma<128, 32, 32>,  cudaFuncAttributeMaxDynamicSharedMemorySize, 53248);
    cudaFuncSetAttribute(k_gemm_mma<32, 32, 32>,   cudaFuncAttributeMaxDynamicSharedMemorySize, 14848);

    int NB = (n + 1023) / 1024;
    int eg = (E + 255) / 256;
    int gb = (n + 127) / 128;
    int g_warp = (n * 32 + 255) / 256;
    int g_16   = (n * 16 + 255) / 256;
    int g_4    = (n * 4 + 255) / 256;

    // weight pack (independent)
    k_pack<<<(45056 + 255) / 256, 256>>>(Wl2, Wr2, Wl3, Wr3, Wl4, Wr4, Wl5, Wr5,
                                         p_w2, p_w3, p_w4, p_w5);

    // CSR build
    cudaMemsetAsync(p_cnt, 0, n * sizeof(int));
    k_count<<<eg, 256>>>(ei, p_cnt, E);
    k_reduce<<<NB, 256>>>(p_cnt, p_bsum, n);
    k_spine<<<1, 128>>>(p_bsum, NB);
    k_scan<<<NB, 256>>>(p_cnt, p_bsum, p_rowptr, p_cursor, n);
    k_fill<<<eg, 256>>>(ei, p_cursor, p_csrc, E);

    // layer 1 (2 -> 128)
    k_layer1<<<g_warp, 256>>>(x, p_rowptr, p_csrc, Wl1, bl1, Wr1, p_h, n);

    // layer 2 (128 -> 128)
    k_gemm_mma<128, 128, 64><<<gb, 512, 102400>>>(p_h, p_w2, p_hl, p_hr, n);
    k_post<128><<<g_16, 256>>>(p_rowptr, p_csrc, p_hl, p_hr, bl2, p_h, n);

    // layer 3 (128 -> 32)
    k_gemm_mma<128, 32, 32><<<gb, 256, 53248>>>(p_h, p_w3, p_hl, p_hr, n);
    k_post<32><<<g_4, 256>>>(p_rowptr, p_csrc, p_hl, p_hr, bl3, p_h, n);

    // layer 4 (32 -> 32)
    k_gemm_mma<32, 32, 32><<<gb, 256, 14848>>>(p_h, p_w4, p_hl, p_hr, n);
    k_post<32><<<g_4, 256>>>(p_rowptr, p_csrc, p_hl, p_hr, bl4, p_h, n);

    // layer 5 (32 -> 32) + fused output head
    k_gemm_mma<32, 32, 32><<<gb, 256, 14848>>>(p_h, p_w5, p_hl, p_hr, n);
    k_post_out<<<g_4, 256>>>(p_rowptr, p_csrc, p_hl, p_hr, bl5, Wo, bo, out, n);
}